// round 1
// baseline (speedup 1.0000x reference)
#include <cuda_runtime.h>
#include <math.h>

#define NB   32
#define CC   256
#define HH   64
#define WW   64
#define HW   4096        // 64*64
#define QQ   1600        // 25*64
#define K25  25

// ---------------- scratch (device globals; no allocation allowed) ----------
__device__ float                 g_w2sum[CC];
__device__ int                   g_t3i[NB * CC];          // t3 as float bits (>=0)
__device__ __align__(16) float   g_s1[NB * HW];           // sum_c w2sum[c]*relu(x)
__device__ __align__(16) float   g_t5[NB * HW];
__device__ float                 g_t7[NB * K25 * WW];     // [n][k][w]
__device__ float                 g_weff[QQ * K25];        // W10 @ W8, row q contiguous
__device__ int                   g_Mi[NB * WW];           // max_q exp(t12) as float bits (>0)

// ---------------- Kprep: Weff = W10@W8, w2sum = colsum(W2), zero atomics ---
__global__ void kprep(const float* __restrict__ W2,
                      const float* __restrict__ W8,
                      const float* __restrict__ W10) {
    int g = blockIdx.x * blockDim.x + threadIdx.x;
    if (g < QQ * K25) {
        int q = g / K25, k = g % K25;
        float s = 0.f;
        const float* w10r = W10 + q * CC;
        #pragma unroll 4
        for (int o = 0; o < CC; o++) s = fmaf(w10r[o], W8[o * K25 + k], s);
        g_weff[g] = s;
    }
    if (g < NB * CC) g_t3i[g] = 0;
    if (g < NB * WW) g_Mi[g] = 0;
    if (g < CC) {
        float s = 0.f;
        #pragma unroll 4
        for (int o = 0; o < CC; o++) s += W2[o * CC + g];
        g_w2sum[g] = s;
    }
}

// ---------------- K1: pass 1 over x -> s1[n,h,w] and t3[n,c] ---------------
// grid = NB*8 blocks (tile of 512 pixels), 128 threads, float4 per thread
__global__ void k1(const float* __restrict__ x) {
    __shared__ float sw[CC];
    int n    = blockIdx.x >> 3;
    int tile = blockIdx.x & 7;
    sw[threadIdx.x]       = g_w2sum[threadIdx.x];
    sw[threadIdx.x + 128] = g_w2sum[threadIdx.x + 128];
    __syncthreads();

    const float4* xp = (const float4*)(x + (size_t)n * CC * HW + tile * 512) + threadIdx.x;
    int* t3p = g_t3i + n * CC;
    float4 acc = make_float4(0.f, 0.f, 0.f, 0.f);

    #pragma unroll 4
    for (int c = 0; c < CC; c++) {
        float4 v = xp[c * (HW / 4)];
        float r0 = fmaxf(v.x, 0.f), r1 = fmaxf(v.y, 0.f);
        float r2 = fmaxf(v.z, 0.f), r3 = fmaxf(v.w, 0.f);
        float w = sw[c];
        acc.x = fmaf(w, r0, acc.x);
        acc.y = fmaf(w, r1, acc.y);
        acc.z = fmaf(w, r2, acc.z);
        acc.w = fmaf(w, r3, acc.w);
        float m = fmaxf(fmaxf(r0, r1), fmaxf(r2, r3));
        #pragma unroll
        for (int off = 16; off; off >>= 1)
            m = fmaxf(m, __shfl_xor_sync(0xffffffffu, m, off));
        if ((threadIdx.x & 31) == 0)
            atomicMax(&t3p[c], __float_as_int(m));   // values >= 0: int order == float order
    }
    *((float4*)(g_s1 + n * HW + tile * 512) + threadIdx.x) = acc;
}

// ---------------- K2: t5 = p4*s1/C (padded in smem) -> t7[n,k,w] -----------
// grid = NB blocks, 256 threads
__global__ void k2(const float* __restrict__ p4) {
    __shared__ float sm[76 * 76];   // t5 padded by 6 each side
    int n = blockIdx.x;
    for (int i = threadIdx.x; i < 76 * 76; i += 256) sm[i] = 0.f;
    __syncthreads();
    for (int i = threadIdx.x; i < HW; i += 256) {
        int h = i >> 6, w = i & 63;
        float v = g_s1[n * HW + i] * p4[i] * (1.0f / 256.0f);
        sm[(h + 6) * 76 + (w + 6)] = v;
        g_t5[n * HW + i] = v;
    }
    __syncthreads();
    for (int idx = threadIdx.x; idx < K25 * WW; idx += 256) {
        int k = idx >> 6, w = idx & 63;
        int ki = k / 5, kj = k % 5;
        const float* row = sm + (3 * ki) * 76 + (w + 3 * kj);
        float m = -INFINITY;
        #pragma unroll
        for (int h = 0; h < HH; h++) m = fmaxf(m, row[h * 76]);
        g_t7[n * (K25 * WW) + idx] = m;
    }
}

// ---------------- K3: t10/gelu/exp, column max -> M[n,w] -------------------
// grid = NB*25 blocks (one (n,k)), 256 threads
__global__ void k3() {
    __shared__ float s5[HW];            // t5[n]
    __shared__ float s7[K25 * WW];      // t7[n][k'][w]
    __shared__ float swf[HH * K25];     // weff rows q=k*64+h
    __shared__ float smax[4 * WW];

    int n = blockIdx.x / K25;
    int k = blockIdx.x % K25;

    {
        const float4* src = (const float4*)(g_t5 + n * HW);
        float4* dst = (float4*)s5;
        for (int i = threadIdx.x; i < HW / 4; i += 256) dst[i] = src[i];
    }
    for (int i = threadIdx.x; i < K25 * WW; i += 256) s7[i] = g_t7[n * (K25 * WW) + i];
    for (int i = threadIdx.x; i < HH * K25; i += 256) swf[i] = g_weff[k * (HH * K25) + i];
    __syncthreads();

    int w  = threadIdx.x & 63;
    int hq = threadIdx.x >> 6;          // 0..3
    float t7c[K25];
    #pragma unroll
    for (int kk = 0; kk < K25; kk++) t7c[kk] = s7[kk * WW + w];

    int ki = k / 5, kj = k % 5;
    int cs = w + 3 * kj - 6;
    bool cok = (cs >= 0) && (cs < WW);

    float mymax = 0.f;                   // exp(.) > 0 always
    for (int hb = 0; hb < 16; hb++) {
        int h = hq * 16 + hb;
        float t10 = 0.f;
        const float* wr = swf + h * K25;
        #pragma unroll
        for (int kk = 0; kk < K25; kk++) t10 = fmaf(wr[kk], t7c[kk], t10);
        float gl = 0.5f * t10 * (1.0f + erff(t10 * 0.70710678118654752f));  // exact gelu
        int rs = h + 3 * ki - 6;
        float t6v = (cok && rs >= 0 && rs < HH) ? s5[rs * WW + cs] : 0.f;
        float e = expf(t6v + gl);
        mymax = fmaxf(mymax, e);
    }
    smax[hq * WW + w] = mymax;
    __syncthreads();
    if (threadIdx.x < WW) {
        float m = fmaxf(fmaxf(smax[threadIdx.x], smax[WW + threadIdx.x]),
                        fmaxf(smax[2 * WW + threadIdx.x], smax[3 * WW + threadIdx.x]));
        atomicMax(&g_Mi[n * WW + threadIdx.x], __float_as_int(m));   // values > 0
    }
}

// ---------------- K5: pass 2 over x -> t9, write t19 -----------------------
// grid = NB*8 blocks (tile = 512 px = 8 h-rows), 128 threads, float4/thread
__global__ void k5(const float* __restrict__ x,
                   const float* __restrict__ W18,
                   const float* __restrict__ p13,
                   float* __restrict__ out) {
    __shared__ float st3[CC];
    __shared__ float st17[WW];
    __shared__ float sw18[CC * 8];      // [c][row-in-tile]

    int n = blockIdx.x >> 3;
    int tile = blockIdx.x & 7;
    int h0 = tile * 8;

    st3[threadIdx.x]       = __int_as_float(g_t3i[n * CC + threadIdx.x]);
    st3[threadIdx.x + 128] = __int_as_float(g_t3i[n * CC + threadIdx.x + 128]);
    if (threadIdx.x < WW) {
        float s = 0.f;
        #pragma unroll
        for (int j = 0; j < 7; j++) {
            int p = threadIdx.x - 9 + 3 * j;
            if (p >= 0 && p < WW) s += __int_as_float(g_Mi[n * WW + p]);
        }
        st17[threadIdx.x] = s * (1.0f / 7.0f);
    }
    for (int i = threadIdx.x; i < CC * 8; i += 128) {
        int c = i >> 3, r = i & 7;
        sw18[i] = W18[c * HH + h0 + r];
    }
    __syncthreads();

    int px = threadIdx.x * 4;                 // 0..508 within tile
    int hr = px >> 6;                          // 0..7
    int h  = h0 + hr;
    int w  = px & 63;

    const float4* xp = (const float4*)(x + (size_t)n * CC * HW + tile * 512) + threadIdx.x;
    float4 acc = make_float4(0.f, 0.f, 0.f, 0.f);
    #pragma unroll 4
    for (int c = 0; c < CC; c++) {
        float4 v = xp[c * (HW / 4)];
        float t = st3[c];
        acc.x = fmaf(t, v.x, acc.x);
        acc.y = fmaf(t, v.y, acc.y);
        acc.z = fmaf(t, v.z, acc.z);
        acc.w = fmaf(t, v.w, acc.w);
    }
    float4 pv = *(const float4*)(p13 + h * WW + w);
    float4 t13 = make_float4(pv.x * acc.x, pv.y * acc.y, pv.z * acc.z, pv.w * acc.w);
    float4 t17v = make_float4(st17[w], st17[w + 1], st17[w + 2], st17[w + 3]);

    float4* op = (float4*)(out + (size_t)n * CC * HW + tile * 512) + threadIdx.x;
    #pragma unroll 4
    for (int c = 0; c < CC; c++) {
        float wv = sw18[c * 8 + hr];
        float4 o;
        o.x = fmaf(-wv, t17v.x, t13.x);
        o.y = fmaf(-wv, t17v.y, t13.y);
        o.z = fmaf(-wv, t17v.z, t13.z);
        o.w = fmaf(-wv, t17v.w, t13.w);
        op[c * (HW / 4)] = o;
    }
}

// ---------------------------------------------------------------------------
extern "C" void kernel_launch(void* const* d_in, const int* in_sizes, int n_in,
                              void* d_out, int out_size) {
    const float* x   = (const float*)d_in[0];
    const float* W2  = (const float*)d_in[1];
    const float* W8  = (const float*)d_in[2];
    const float* W10 = (const float*)d_in[3];
    const float* W18 = (const float*)d_in[4];
    const float* p4  = (const float*)d_in[5];
    const float* p13 = (const float*)d_in[6];
    float* out = (float*)d_out;

    kprep<<<(QQ * K25 + 255) / 256, 256>>>(W2, W8, W10);
    k1<<<NB * 8, 128>>>(x);
    k2<<<NB, 256>>>(p4);
    k3<<<NB * K25, 256>>>();
    k5<<<NB * 8, 128>>>(x, W18, p13, out);
}

// round 2
// speedup vs baseline: 1.6700x; 1.6700x over previous
#include <cuda_runtime.h>
#include <math.h>

#define NB   32
#define CC   256
#define HH   64
#define WW   64
#define HW   4096        // 64*64
#define QQ   1600        // 25*64
#define K25  25

// ---------------- scratch (device globals) ---------------------------------
__device__ float                 g_w2sum[CC];
__device__ int                   g_t3i[NB * CC];        // t3 as float bits (>=0)
__device__ __align__(16) float   g_t5[NB * HW];         // p4 * mean_o(t2)
__device__ __align__(16) float   g_t13[NB * HW];        // p13 * t9
__device__ float                 g_t7[NB * K25 * WW];   // [n][k][w]
__device__ float                 g_weff[QQ * K25];      // W10 @ W8
__device__ unsigned              g_Mu[NB * WW];         // max_q t12, order-encoded

__device__ __forceinline__ unsigned encf(float x) {
    unsigned u = __float_as_uint(x);
    return (u & 0x80000000u) ? ~u : (u | 0x80000000u);
}
__device__ __forceinline__ float decf(unsigned u) {
    return __uint_as_float((u & 0x80000000u) ? (u ^ 0x80000000u) : ~u);
}

// ---------------- Kprep ----------------------------------------------------
__global__ void kprep(const float* __restrict__ W2,
                      const float* __restrict__ W8,
                      const float* __restrict__ W10) {
    int g = blockIdx.x * blockDim.x + threadIdx.x;
    if (g < QQ * K25) {
        int q = g / K25, k = g % K25;
        float s = 0.f;
        const float* w10r = W10 + q * CC;
        #pragma unroll 4
        for (int o = 0; o < CC; o++) s = fmaf(w10r[o], W8[o * K25 + k], s);
        g_weff[g] = s;
    }
    if (g < NB * CC) g_t3i[g] = 0;
    if (g < NB * WW) g_Mu[g] = 0u;          // below any real encoded value
    if (g < CC) {
        float s = 0.f;
        #pragma unroll 4
        for (int o = 0; o < CC; o++) s += W2[o * CC + g];
        g_w2sum[g] = s;
    }
}

// ---------------- K1: pass 1 over x -> t5[n,h,w] and t3[n,c] ---------------
// grid = NB*16 blocks (tile of 256 px), 256 threads (8 warps x 32 channels)
__global__ void k1(const float* __restrict__ x, const float* __restrict__ p4) {
    __shared__ float sw[CC];
    __shared__ float sred[8 * 256];
    int n = blockIdx.x >> 4, tile = blockIdx.x & 15;
    int tid = threadIdx.x, warp = tid >> 5, lane = tid & 31;
    sw[tid] = g_w2sum[tid];
    __syncthreads();

    const float4* xb = (const float4*)x + (size_t)n * CC * (HW / 4) + tile * 64;
    int* t3p = g_t3i + n * CC;
    float4 a0 = make_float4(0.f, 0.f, 0.f, 0.f), a1 = a0;

    #pragma unroll 4
    for (int i = 0; i < 32; i++) {
        int c = warp + 8 * i;
        const float4* p = xb + (size_t)c * (HW / 4) + lane;
        float4 v0 = p[0], v1 = p[32];
        v0.x = fmaxf(v0.x, 0.f); v0.y = fmaxf(v0.y, 0.f);
        v0.z = fmaxf(v0.z, 0.f); v0.w = fmaxf(v0.w, 0.f);
        v1.x = fmaxf(v1.x, 0.f); v1.y = fmaxf(v1.y, 0.f);
        v1.z = fmaxf(v1.z, 0.f); v1.w = fmaxf(v1.w, 0.f);
        float wv = sw[c];
        a0.x = fmaf(wv, v0.x, a0.x); a0.y = fmaf(wv, v0.y, a0.y);
        a0.z = fmaf(wv, v0.z, a0.z); a0.w = fmaf(wv, v0.w, a0.w);
        a1.x = fmaf(wv, v1.x, a1.x); a1.y = fmaf(wv, v1.y, a1.y);
        a1.z = fmaf(wv, v1.z, a1.z); a1.w = fmaf(wv, v1.w, a1.w);
        float m = fmaxf(fmaxf(fmaxf(v0.x, v0.y), fmaxf(v0.z, v0.w)),
                        fmaxf(fmaxf(v1.x, v1.y), fmaxf(v1.z, v1.w)));
        #pragma unroll
        for (int off = 16; off; off >>= 1)
            m = fmaxf(m, __shfl_xor_sync(0xffffffffu, m, off));
        if (lane == 0) atomicMax(&t3p[c], __float_as_int(m));   // relu >= 0
    }
    float4* sr = (float4*)sred + warp * 64 + lane;
    sr[0] = a0; sr[32] = a1;
    __syncthreads();
    if (tid < 256) {
        float s = 0.f;
        #pragma unroll
        for (int w = 0; w < 8; w++) s += sred[w * 256 + tid];
        int px = tile * 256 + tid;
        g_t5[n * HW + px] = s * p4[px] * (1.0f / 256.0f);
    }
}

// ---------------- K2: dilated-patch column max -> t7[n,k,w] ----------------
// grid = NB*25 blocks (one (n,k)), 64 threads
__global__ void k2() {
    int n = blockIdx.x / K25, k = blockIdx.x % K25;
    int ki = k / 5, kj = k % 5;
    int w = threadIdx.x;
    int cs = w + 3 * kj - 6;
    bool cok = (cs >= 0) && (cs < WW);
    const float* t5n = g_t5 + n * HW;
    float m = -INFINITY;
    #pragma unroll
    for (int h = 0; h < HH; h++) {
        int rs = h + 3 * ki - 6;
        float v = (cok && rs >= 0 && rs < HH) ? t5n[rs * WW + cs] : 0.f;
        m = fmaxf(m, v);
    }
    g_t7[n * (K25 * WW) + k * WW + w] = m;
}

// ---------------- K3: t10/gelu, column max of t12 -> g_Mu ------------------
// grid = NB*25 blocks, 256 threads
__global__ void k3() {
    __shared__ float s5[HW];
    __shared__ float s7[K25 * WW];
    __shared__ float swf[HH * K25];
    __shared__ float smax[4 * WW];

    int n = blockIdx.x / K25;
    int k = blockIdx.x % K25;

    {
        const float4* src = (const float4*)(g_t5 + n * HW);
        float4* dst = (float4*)s5;
        for (int i = threadIdx.x; i < HW / 4; i += 256) dst[i] = src[i];
    }
    for (int i = threadIdx.x; i < K25 * WW; i += 256) s7[i] = g_t7[n * (K25 * WW) + i];
    for (int i = threadIdx.x; i < HH * K25; i += 256) swf[i] = g_weff[k * (HH * K25) + i];
    __syncthreads();

    int w  = threadIdx.x & 63;
    int hq = threadIdx.x >> 6;
    float t7c[K25];
    #pragma unroll
    for (int kk = 0; kk < K25; kk++) t7c[kk] = s7[kk * WW + w];

    int ki = k / 5, kj = k % 5;
    int cs = w + 3 * kj - 6;
    bool cok = (cs >= 0) && (cs < WW);

    float mymax = -INFINITY;
    for (int hb = 0; hb < 16; hb++) {
        int h = hq * 16 + hb;
        float t10 = 0.f;
        const float* wr = swf + h * K25;
        #pragma unroll
        for (int kk = 0; kk < K25; kk++) t10 = fmaf(wr[kk], t7c[kk], t10);
        float gl = 0.5f * t10 * (1.0f + erff(t10 * 0.70710678118654752f));
        int rs = h + 3 * ki - 6;
        float t6v = (cok && rs >= 0 && rs < HH) ? s5[rs * WW + cs] : 0.f;
        mymax = fmaxf(mymax, t6v + gl);      // exp is monotone: defer it
    }
    smax[hq * WW + w] = mymax;
    __syncthreads();
    if (threadIdx.x < WW) {
        float m = fmaxf(fmaxf(smax[threadIdx.x], smax[WW + threadIdx.x]),
                        fmaxf(smax[2 * WW + threadIdx.x], smax[3 * WW + threadIdx.x]));
        atomicMax(&g_Mu[n * WW + threadIdx.x], encf(m));
    }
}

// ---------------- K5a: pass 2 over x -> t13 = p13 * (t3 . x) ---------------
// grid = NB*16 blocks (tile of 256 px), 256 threads (8 warps x 32 channels)
__global__ void k5a(const float* __restrict__ x, const float* __restrict__ p13) {
    __shared__ float st3[CC];
    __shared__ float sred[8 * 256];
    int n = blockIdx.x >> 4, tile = blockIdx.x & 15;
    int tid = threadIdx.x, warp = tid >> 5, lane = tid & 31;
    st3[tid] = __int_as_float(g_t3i[n * CC + tid]);
    __syncthreads();

    const float4* xb = (const float4*)x + (size_t)n * CC * (HW / 4) + tile * 64;
    float4 a0 = make_float4(0.f, 0.f, 0.f, 0.f), a1 = a0;

    #pragma unroll 4
    for (int i = 0; i < 32; i++) {
        int c = warp + 8 * i;
        const float4* p = xb + (size_t)c * (HW / 4) + lane;
        float4 v0 = p[0], v1 = p[32];
        float t = st3[c];
        a0.x = fmaf(t, v0.x, a0.x); a0.y = fmaf(t, v0.y, a0.y);
        a0.z = fmaf(t, v0.z, a0.z); a0.w = fmaf(t, v0.w, a0.w);
        a1.x = fmaf(t, v1.x, a1.x); a1.y = fmaf(t, v1.y, a1.y);
        a1.z = fmaf(t, v1.z, a1.z); a1.w = fmaf(t, v1.w, a1.w);
    }
    float4* sr = (float4*)sred + warp * 64 + lane;
    sr[0] = a0; sr[32] = a1;
    __syncthreads();
    if (tid < 256) {
        float s = 0.f;
        #pragma unroll
        for (int w = 0; w < 8; w++) s += sred[w * 256 + tid];
        int px = tile * 256 + tid;
        g_t13[n * HW + px] = s * p13[px];
    }
}

// ---------------- K5b: streaming write of t19 ------------------------------
// grid = NB*64 blocks (one n, 4 channels), 256 threads
__global__ void k5b(const float* __restrict__ W18, float* __restrict__ out) {
    __shared__ float s13[HW];
    __shared__ float sW18[4 * HH];
    __shared__ float st17[WW];

    int n  = blockIdx.x >> 6;
    int c0 = (blockIdx.x & 63) * 4;
    int tid = threadIdx.x;

    {
        const float4* src = (const float4*)(g_t13 + n * HW);
        float4* dst = (float4*)s13;
        for (int i = tid; i < HW / 4; i += 256) dst[i] = src[i];
    }
    if (tid < WW) {
        float s = 0.f;
        #pragma unroll
        for (int j = 0; j < 7; j++) {
            int p = tid - 9 + 3 * j;
            if (p >= 0 && p < WW) s += expf(decf(g_Mu[n * WW + p]));
        }
        st17[tid] = s * (1.0f / 7.0f);
    }
    if (tid < 4 * HH) {
        int c = tid >> 6, h = tid & 63;
        sW18[tid] = W18[(c0 + c) * HH + h];
    }
    __syncthreads();

    #pragma unroll
    for (int cc = 0; cc < 4; cc++) {
        float4* op = (float4*)out + ((size_t)(n * CC + c0 + cc)) * (HW / 4);
        const float4* sp = (const float4*)s13;
        #pragma unroll
        for (int j = 0; j < 4; j++) {
            int f = tid + 256 * j;          // float4 index within plane
            int h = f >> 4;
            int wb = (f & 15) * 4;
            float wv = sW18[cc * HH + h];
            float4 t = sp[f];
            float4 o;
            o.x = fmaf(-wv, st17[wb + 0], t.x);
            o.y = fmaf(-wv, st17[wb + 1], t.y);
            o.z = fmaf(-wv, st17[wb + 2], t.z);
            o.w = fmaf(-wv, st17[wb + 3], t.w);
            op[f] = o;
        }
    }
}

// ---------------------------------------------------------------------------
extern "C" void kernel_launch(void* const* d_in, const int* in_sizes, int n_in,
                              void* d_out, int out_size) {
    const float* x   = (const float*)d_in[0];
    const float* W2  = (const float*)d_in[1];
    const float* W8  = (const float*)d_in[2];
    const float* W10 = (const float*)d_in[3];
    const float* W18 = (const float*)d_in[4];
    const float* p4  = (const float*)d_in[5];
    const float* p13 = (const float*)d_in[6];
    float* out = (float*)d_out;

    kprep<<<(QQ * K25 + 255) / 256, 256>>>(W2, W8, W10);
    k1<<<NB * 16, 256>>>(x, p4);
    k2<<<NB * K25, 64>>>();
    k3<<<NB * K25, 256>>>();
    k5a<<<NB * 16, 256>>>(x, p13);
    k5b<<<NB * 64, 256>>>(W18, out);
}

// round 4
// speedup vs baseline: 1.7116x; 1.0249x over previous
#include <cuda_runtime.h>
#include <math.h>

#define NB   32
#define CC   256
#define HH   64
#define WW   64
#define HW   4096        // 64*64
#define QQ   1600        // 25*64
#define K25  25

// ---------------- scratch (device globals) ---------------------------------
__device__ float                 g_w2sum[CC];
__device__ int                   g_t3i[NB * CC];        // t3 as float bits (>=0)
__device__ __align__(16) float   g_t5[NB * HW];         // p4 * mean_o(t2)
__device__ float                 g_t7[NB * K25 * WW];   // [n][k][w]
__device__ float                 g_weff[QQ * K25];      // W10 @ W8
__device__ unsigned              g_Mu[NB * WW];         // max_q t12, order-encoded

__device__ __forceinline__ unsigned encf(float x) {
    unsigned u = __float_as_uint(x);
    return (u & 0x80000000u) ? ~u : (u | 0x80000000u);
}
__device__ __forceinline__ float decf(unsigned u) {
    return __uint_as_float((u & 0x80000000u) ? (u ^ 0x80000000u) : ~u);
}

// ---------------- Kprep ----------------------------------------------------
__global__ void kprep(const float* __restrict__ W2,
                      const float* __restrict__ W8,
                      const float* __restrict__ W10) {
    int g = blockIdx.x * blockDim.x + threadIdx.x;
    if (g < QQ * K25) {
        int q = g / K25, k = g % K25;
        float s = 0.f;
        const float* w10r = W10 + q * CC;
        #pragma unroll 4
        for (int o = 0; o < CC; o++) s = fmaf(w10r[o], W8[o * K25 + k], s);
        g_weff[g] = s;
    }
    if (g < NB * CC) g_t3i[g] = 0;
    if (g < NB * WW) g_Mu[g] = 0u;
    if (g < CC) {
        float s = 0.f;
        #pragma unroll 4
        for (int o = 0; o < CC; o++) s += W2[o * CC + g];
        g_w2sum[g] = s;
    }
}

// ---------------- K1: pass 1 over x -> t5[n,h,w] and t3[n,c] ---------------
// grid = NB*16 blocks (tile of 256 px), 256 threads (8 warps x 32 channels)
// No cross-lane reduce in the hot loop: lane-max goes to padded smem.
__global__ void k1(const float* __restrict__ x, const float* __restrict__ p4) {
    __shared__ float sw[CC];
    __shared__ float sred[8 * 256];     //  8 KB
    __shared__ float smax[CC * 33];     // 33 KB padded (stride 33: conflict-free)
    int n = blockIdx.x >> 4, tile = blockIdx.x & 15;
    int tid = threadIdx.x, warp = tid >> 5, lane = tid & 31;
    sw[tid] = g_w2sum[tid];
    __syncthreads();

    const float4* xb = (const float4*)x + (size_t)n * CC * (HW / 4) + tile * 64;
    float4 a0 = make_float4(0.f, 0.f, 0.f, 0.f), a1 = a0;

    #pragma unroll 4
    for (int i = 0; i < 32; i++) {
        int c = warp + 8 * i;
        const float4* p = xb + (size_t)c * (HW / 4) + lane;
        float4 v0 = p[0], v1 = p[32];
        v0.x = fmaxf(v0.x, 0.f); v0.y = fmaxf(v0.y, 0.f);
        v0.z = fmaxf(v0.z, 0.f); v0.w = fmaxf(v0.w, 0.f);
        v1.x = fmaxf(v1.x, 0.f); v1.y = fmaxf(v1.y, 0.f);
        v1.z = fmaxf(v1.z, 0.f); v1.w = fmaxf(v1.w, 0.f);
        float wv = sw[c];
        a0.x = fmaf(wv, v0.x, a0.x); a0.y = fmaf(wv, v0.y, a0.y);
        a0.z = fmaf(wv, v0.z, a0.z); a0.w = fmaf(wv, v0.w, a0.w);
        a1.x = fmaf(wv, v1.x, a1.x); a1.y = fmaf(wv, v1.y, a1.y);
        a1.z = fmaf(wv, v1.z, a1.z); a1.w = fmaf(wv, v1.w, a1.w);
        smax[c * 33 + lane] = fmaxf(fmaxf(fmaxf(v0.x, v0.y), fmaxf(v0.z, v0.w)),
                                    fmaxf(fmaxf(v1.x, v1.y), fmaxf(v1.z, v1.w)));
    }
    float4* sr = (float4*)sred + warp * 64 + lane;
    sr[0] = a0; sr[32] = a1;
    __syncthreads();

    // sum reduce -> t5
    {
        float s = 0.f;
        #pragma unroll
        for (int w = 0; w < 8; w++) s += sred[w * 256 + tid];
        int px = tile * 256 + tid;
        g_t5[n * HW + px] = s * p4[px] * (1.0f / 256.0f);
    }
    // max reduce: thread tid owns channel tid (stride-33 reads: conflict-free)
    {
        float m = 0.f;
        #pragma unroll
        for (int l = 0; l < 32; l++) m = fmaxf(m, smax[tid * 33 + l]);
        atomicMax(&g_t3i[n * CC + tid], __float_as_int(m));   // relu >= 0
    }
}

// ---------------- K2: dilated-patch column max -> t7[n,k,w] ----------------
__global__ void k2() {
    int n = blockIdx.x / K25, k = blockIdx.x % K25;
    int ki = k / 5, kj = k % 5;
    int w = threadIdx.x;
    int cs = w + 3 * kj - 6;
    bool cok = (cs >= 0) && (cs < WW);
    const float* t5n = g_t5 + n * HW;
    float m = -INFINITY;
    #pragma unroll
    for (int h = 0; h < HH; h++) {
        int rs = h + 3 * ki - 6;
        float v = (cok && rs >= 0 && rs < HH) ? t5n[rs * WW + cs] : 0.f;
        m = fmaxf(m, v);
    }
    g_t7[n * (K25 * WW) + k * WW + w] = m;
}

// ---------------- K3: t10/gelu, column max of t12 -> g_Mu ------------------
__global__ void k3() {
    __shared__ float s5[HW];
    __shared__ float s7[K25 * WW];
    __shared__ float swf[HH * K25];
    __shared__ float smax[4 * WW];

    int n = blockIdx.x / K25;
    int k = blockIdx.x % K25;

    {
        const float4* src = (const float4*)(g_t5 + n * HW);
        float4* dst = (float4*)s5;
        for (int i = threadIdx.x; i < HW / 4; i += 256) dst[i] = src[i];
    }
    for (int i = threadIdx.x; i < K25 * WW; i += 256) s7[i] = g_t7[n * (K25 * WW) + i];
    for (int i = threadIdx.x; i < HH * K25; i += 256) swf[i] = g_weff[k * (HH * K25) + i];
    __syncthreads();

    int w  = threadIdx.x & 63;
    int hq = threadIdx.x >> 6;
    float t7c[K25];
    #pragma unroll
    for (int kk = 0; kk < K25; kk++) t7c[kk] = s7[kk * WW + w];

    int ki = k / 5, kj = k % 5;
    int cs = w + 3 * kj - 6;
    bool cok = (cs >= 0) && (cs < WW);

    float mymax = -INFINITY;
    #pragma unroll 4
    for (int hb = 0; hb < 16; hb++) {
        int h = hq * 16 + hb;
        float t10 = 0.f;
        const float* wr = swf + h * K25;
        #pragma unroll
        for (int kk = 0; kk < K25; kk++) t10 = fmaf(wr[kk], t7c[kk], t10);
        float gl = 0.5f * t10 * (1.0f + erff(t10 * 0.70710678118654752f));
        int rs = h + 3 * ki - 6;
        float t6v = (cok && rs >= 0 && rs < HH) ? s5[rs * WW + cs] : 0.f;
        mymax = fmaxf(mymax, t6v + gl);      // exp is monotone: defer it
    }
    smax[hq * WW + w] = mymax;
    __syncthreads();
    if (threadIdx.x < WW) {
        float m = fmaxf(fmaxf(smax[threadIdx.x], smax[WW + threadIdx.x]),
                        fmaxf(smax[2 * WW + threadIdx.x], smax[3 * WW + threadIdx.x]));
        atomicMax(&g_Mu[n * WW + threadIdx.x], encf(m));
    }
}

// ---------------- K5: pass 2 over x -> t13, then write all 256 channels ----
// grid = NB*16 blocks (tile of 256 px = 4 h-rows), 256 threads
__global__ void k5(const float* __restrict__ x, const float* __restrict__ p13,
                   const float* __restrict__ W18, float* __restrict__ out) {
    __shared__ float st3[CC];
    __shared__ float sred[8 * 256];
    __shared__ __align__(16) float s13[256];
    __shared__ __align__(16) float st17[WW];
    __shared__ float sW18[CC * 4];     // [c][hr], hr = row within tile

    int n = blockIdx.x >> 4, tile = blockIdx.x & 15;
    int tid = threadIdx.x, warp = tid >> 5, lane = tid & 31;
    int h0 = tile * 4;

    st3[tid] = __int_as_float(g_t3i[n * CC + tid]);
    ((float4*)sW18)[tid] = *(const float4*)(W18 + tid * HH + h0);   // c=tid, 4 rows
    if (tid < WW) {
        float s = 0.f;
        #pragma unroll
        for (int j = 0; j < 7; j++) {
            int p = tid - 9 + 3 * j;
            if (p >= 0 && p < WW) s += expf(decf(g_Mu[n * WW + p]));
        }
        st17[tid] = s * (1.0f / 7.0f);
    }
    __syncthreads();

    const float4* xb = (const float4*)x + (size_t)n * CC * (HW / 4) + tile * 64;
    float4 a0 = make_float4(0.f, 0.f, 0.f, 0.f), a1 = a0;
    #pragma unroll 4
    for (int i = 0; i < 32; i++) {
        int c = warp + 8 * i;
        const float4* p = xb + (size_t)c * (HW / 4) + lane;
        float4 v0 = p[0], v1 = p[32];
        float t = st3[c];
        a0.x = fmaf(t, v0.x, a0.x); a0.y = fmaf(t, v0.y, a0.y);
        a0.z = fmaf(t, v0.z, a0.z); a0.w = fmaf(t, v0.w, a0.w);
        a1.x = fmaf(t, v1.x, a1.x); a1.y = fmaf(t, v1.y, a1.y);
        a1.z = fmaf(t, v1.z, a1.z); a1.w = fmaf(t, v1.w, a1.w);
    }
    float4* sr = (float4*)sred + warp * 64 + lane;
    sr[0] = a0; sr[32] = a1;
    __syncthreads();
    {
        float s = 0.f;
        #pragma unroll
        for (int w = 0; w < 8; w++) s += sred[w * 256 + tid];
        s13[tid] = s * p13[tile * 256 + tid];
    }
    __syncthreads();

    // write phase: 256 channels x 256 px for this tile
    float4* ob = (float4*)out + (size_t)n * CC * (HW / 4) + tile * 64;
    #pragma unroll 8
    for (int j = 0; j < 64; j++) {
        int idx = j * 256 + tid;       // 0..16383
        int c   = idx >> 6;
        int f4  = idx & 63;            // float4 index within the 256-px tile
        int hr  = f4 >> 4;
        int wq  = f4 & 15;
        float wv   = sW18[c * 4 + hr];
        float4 t   = ((const float4*)s13)[f4];
        float4 t17 = ((const float4*)st17)[wq];
        float4 o;
        o.x = fmaf(-wv, t17.x, t.x);
        o.y = fmaf(-wv, t17.y, t.y);
        o.z = fmaf(-wv, t17.z, t.z);
        o.w = fmaf(-wv, t17.w, t.w);
        ob[(size_t)c * (HW / 4) + f4] = o;
    }
}

// ---------------------------------------------------------------------------
extern "C" void kernel_launch(void* const* d_in, const int* in_sizes, int n_in,
                              void* d_out, int out_size) {
    const float* x   = (const float*)d_in[0];
    const float* W2  = (const float*)d_in[1];
    const float* W8  = (const float*)d_in[2];
    const float* W10 = (const float*)d_in[3];
    const float* W18 = (const float*)d_in[4];
    const float* p4  = (const float*)d_in[5];
    const float* p13 = (const float*)d_in[6];
    float* out = (float*)d_out;

    kprep<<<(QQ * K25 + 255) / 256, 256>>>(W2, W8, W10);
    k1<<<NB * 16, 256>>>(x, p4);
    k2<<<NB * K25, 64>>>();
    k3<<<NB * K25, 256>>>();
    k5<<<NB * 16, 256>>>(x, p13, W18, out);
}